// round 8
// baseline (speedup 1.0000x reference)
#include <cuda_runtime.h>
#include <cstddef>

#define BB 2048
#define NN 512
#define XX 32
#define HH 64
#define TILE_B 8
#define THREADS 128
#define NBLK (BB / TILE_B)   /* 256 */
#define HPITCH 12            /* 48B pitch: 16B-aligned */
#define GPITCH 65

__device__ __forceinline__ unsigned long long pack2(float v) {
    unsigned long long r;
    asm("mov.b64 %0, {%1, %1};" : "=l"(r) : "f"(v));
    return r;
}
__device__ __forceinline__ unsigned long long fma2(unsigned long long a,
                                                   unsigned long long b,
                                                   unsigned long long c) {
    unsigned long long d;
    asm("fma.rn.f32x2 %0, %1, %2, %3;" : "=l"(d) : "l"(a), "l"(b), "l"(c));
    return d;
}
__device__ __forceinline__ void unpack2(unsigned long long v, float& lo, float& hi) {
    asm("mov.b64 {%0, %1}, %2;" : "=f"(lo), "=f"(hi) : "l"(v));
}

__device__ __forceinline__ float sigmoidf_fast(float x) {
    return __fdividef(1.0f, 1.0f + __expf(-x));
}
__device__ __forceinline__ float tanhf_fast(float x) {
    return __fdividef(2.0f, 1.0f + __expf(-2.0f * x)) - 1.0f;
}

__global__ void __launch_bounds__(THREADS, 2)
timelstm_kernel(const float* __restrict__ x,
                const float* __restrict__ ig_w_c, const float* __restrict__ ig_w_h,
                const float* __restrict__ ig_w_x, const float* __restrict__ ig_b,
                const float* __restrict__ fg_w_c, const float* __restrict__ fg_w_h,
                const float* __restrict__ fg_w_x, const float* __restrict__ fg_b,
                const float* __restrict__ in_w_h, const float* __restrict__ in_w_x,
                const float* __restrict__ in_b,
                const float* __restrict__ og_w_cn, const float* __restrict__ og_w_h,
                const float* __restrict__ og_w_x, const float* __restrict__ og_b,
                float* __restrict__ out)
{
    // ping-pong buffers: [buf][k][row], 16B-aligned rows
    __shared__ __align__(16) float h_sh[2][HH * HPITCH];
    __shared__ __align__(16) float x_sh[2][XX * HPITCH];
    __shared__ float g_sh[4][TILE_B][GPITCH];
    __shared__ float cm_sh[TILE_B][HH];
    __shared__ float wc_sh[3][HH];

    const int tid = threadIdx.x;
    const int b0  = blockIdx.x * TILE_B;
    const int p   = tid >> 6;      // gate pair: 0 -> (ig,fg), 1 -> (in,og)
    const int hid = tid & 63;      // output channel

    // ---- two full weight rows per thread ----
    const float *Wh0, *Wx0, *Bv0, *Wh1, *Wx1, *Bv1;
    if (p == 0) { Wh0 = ig_w_h; Wx0 = ig_w_x; Bv0 = ig_b;
                  Wh1 = fg_w_h; Wx1 = fg_w_x; Bv1 = fg_b; }
    else        { Wh0 = in_w_h; Wx0 = in_w_x; Bv0 = in_b;
                  Wh1 = og_w_h; Wx1 = og_w_x; Bv1 = og_b; }

    float w0x[XX], w1x[XX], w0h[HH], w1h[HH];
    #pragma unroll
    for (int j = 0; j < XX; j++) { w0x[j] = Wx0[hid * XX + j]; w1x[j] = Wx1[hid * XX + j]; }
    #pragma unroll
    for (int j = 0; j < HH; j++) { w0h[j] = Wh0[hid * HH + j]; w1h[j] = Wh1[hid * HH + j]; }
    const float bias0 = Bv0[hid];
    const float bias1 = Bv1[hid];

    if (tid < HH) {
        wc_sh[0][tid] = ig_w_c[tid];
        wc_sh[1][tid] = fg_w_c[tid];
        wc_sh[2][tid] = og_w_cn[tid];
    }
    for (int i = tid; i < HH * HPITCH; i += THREADS) h_sh[0][i] = 0.0f;
    for (int i = tid; i < TILE_B * HH; i += THREADS) (&cm_sh[0][0])[i] = 0.0f;

    // ---- x prefetch: 2 values/thread/step (8 rows x 32 k) ----
    const int xr = tid >> 5;   // rows xr and xr+4
    const int xk = tid & 31;
    const float* xp0 = x + ((size_t)(b0 + xr) * NN) * XX + xk;
    const float* xp1 = x + ((size_t)(b0 + xr + 4) * NN) * XX + xk;

    // prologue: deposit x(0) into buf 0, prefetch x(1) into regs
    float xv0 = xp0[0], xv1 = xp1[0];
    x_sh[0][xk * HPITCH + xr]     = xv0;
    x_sh[0][xk * HPITCH + xr + 4] = xv1;
    xv0 = xp0[XX];
    xv1 = xp1[XX];
    __syncthreads();   // x(0), h(0)=0, cm=0 all visible

    // xacc(0): acc = bias + x-projection of step 0
    unsigned long long a0[4], a1[4];
    {
        unsigned long long b0p = pack2(bias0), b1p = pack2(bias1);
        #pragma unroll
        for (int i = 0; i < 4; i++) { a0[i] = b0p; a1[i] = b1p; }
        #pragma unroll
        for (int k = 0; k < XX; k++) {
            const ulonglong2* ptr =
                reinterpret_cast<const ulonglong2*>(&x_sh[0][k * HPITCH]);
            ulonglong2 v0 = ptr[0], v1 = ptr[1];
            unsigned long long u0 = pack2(w0x[k]), u1 = pack2(w1x[k]);
            a0[0] = fma2(v0.x, u0, a0[0]); a0[1] = fma2(v0.y, u0, a0[1]);
            a0[2] = fma2(v1.x, u0, a0[2]); a0[3] = fma2(v1.y, u0, a0[3]);
            a1[0] = fma2(v0.x, u1, a1[0]); a1[1] = fma2(v0.y, u1, a1[1]);
            a1[2] = fma2(v1.x, u1, a1[2]); a1[3] = fma2(v1.y, u1, a1[3]);
        }
    }

    const int rb = tid >> 6;   // phase-B rows rb*4..rb*4+3 (p reused as rb? distinct name)
    const int hh = tid & 63;

    for (int t = 0; t < NN; t++) {
        const int buf  = t & 1;
        const int nbuf = buf ^ 1;

        // ---- W1: deposit x(t+1), then h-projection (acc already holds bias+x(t)) ----
        x_sh[nbuf][xk * HPITCH + xr]     = xv0;
        x_sh[nbuf][xk * HPITCH + xr + 4] = xv1;

        #pragma unroll
        for (int k = 0; k < HH; k++) {
            const ulonglong2* ptr =
                reinterpret_cast<const ulonglong2*>(&h_sh[buf][k * HPITCH]);
            ulonglong2 v0 = ptr[0], v1 = ptr[1];
            unsigned long long u0 = pack2(w0h[k]), u1 = pack2(w1h[k]);
            a0[0] = fma2(v0.x, u0, a0[0]); a0[1] = fma2(v0.y, u0, a0[1]);
            a0[2] = fma2(v1.x, u0, a0[2]); a0[3] = fma2(v1.y, u0, a0[3]);
            a1[0] = fma2(v0.x, u1, a1[0]); a1[1] = fma2(v0.y, u1, a1[1]);
            a1[2] = fma2(v1.x, u1, a1[2]); a1[3] = fma2(v1.y, u1, a1[3]);
        }
        #pragma unroll
        for (int i = 0; i < 4; i++) {
            float lo, hi;
            unpack2(a0[i], lo, hi);
            g_sh[2 * p][2 * i][hid]     = lo;
            g_sh[2 * p][2 * i + 1][hid] = hi;
            unpack2(a1[i], lo, hi);
            g_sh[2 * p + 1][2 * i][hid]     = lo;
            g_sh[2 * p + 1][2 * i + 1][hid] = hi;
        }
        __syncthreads();   // B2: g_sh ready, x(t+1) deposits visible

        // ---- W2: phase B (MUFU) overlapped with xacc(t+1) (fma) ----

        // issue x(t+2) prefetch first (long-latency LDG, consumed next iteration)
        if (t + 2 < NN) {
            xv0 = xp0[(size_t)(t + 2) * XX];
            xv1 = xp1[(size_t)(t + 2) * XX];
        }

        // phase B: 4 rows/thread, rows rb*4..rb*4+3, channel hh
        {
            const float wic = wc_sh[0][hh];
            const float wfc = wc_sh[1][hh];
            const float woc = wc_sh[2][hh];
            float hv[4];
            #pragma unroll
            for (int rr = 0; rr < 4; rr++) {
                const int r = rb * 4 + rr;
                const float cm  = cm_sh[r][hh];
                const float ig  = sigmoidf_fast(wic * cm + g_sh[0][r][hh]);
                const float fg  = sigmoidf_fast(wfc * cm + g_sh[1][r][hh]);
                const float inn = tanhf_fast(g_sh[2][r][hh]);
                const float cmn = fg * cm + ig * inn;
                const float og  = sigmoidf_fast(woc * cmn + g_sh[3][r][hh]);
                hv[rr] = og * tanhf_fast(cmn);
                cm_sh[r][hh] = cmn;
            }
            *reinterpret_cast<float4*>(&h_sh[nbuf][hh * HPITCH + rb * 4]) =
                make_float4(hv[0], hv[1], hv[2], hv[3]);
            if (t == NN - 1) {
                #pragma unroll
                for (int rr = 0; rr < 4; rr++)
                    out[(size_t)(b0 + rb * 4 + rr) * HH + hh] = hv[rr];
            }
        }

        // xacc(t+1): independent fma chains, overlap the MUFU above
        {
            unsigned long long b0p = pack2(bias0), b1p = pack2(bias1);
            #pragma unroll
            for (int i = 0; i < 4; i++) { a0[i] = b0p; a1[i] = b1p; }
            #pragma unroll
            for (int k = 0; k < XX; k++) {
                const ulonglong2* ptr =
                    reinterpret_cast<const ulonglong2*>(&x_sh[nbuf][k * HPITCH]);
                ulonglong2 v0 = ptr[0], v1 = ptr[1];
                unsigned long long u0 = pack2(w0x[k]), u1 = pack2(w1x[k]);
                a0[0] = fma2(v0.x, u0, a0[0]); a0[1] = fma2(v0.y, u0, a0[1]);
                a0[2] = fma2(v1.x, u0, a0[2]); a0[3] = fma2(v1.y, u0, a0[3]);
                a1[0] = fma2(v0.x, u1, a1[0]); a1[1] = fma2(v0.y, u1, a1[1]);
                a1[2] = fma2(v1.x, u1, a1[2]); a1[3] = fma2(v1.y, u1, a1[3]);
            }
        }
        __syncthreads();   // B1: h(t+1) ready; closes the step
    }
}

extern "C" void kernel_launch(void* const* d_in, const int* in_sizes, int n_in,
                              void* d_out, int out_size) {
    const float* x       = (const float*)d_in[0];
    const float* ig_w_c  = (const float*)d_in[1];
    const float* ig_w_h  = (const float*)d_in[2];
    const float* ig_w_x  = (const float*)d_in[3];
    const float* ig_b    = (const float*)d_in[4];
    const float* fg_w_c  = (const float*)d_in[5];
    const float* fg_w_h  = (const float*)d_in[6];
    const float* fg_w_x  = (const float*)d_in[7];
    const float* fg_b    = (const float*)d_in[8];
    const float* in_w_h  = (const float*)d_in[9];
    const float* in_w_x  = (const float*)d_in[10];
    const float* in_b    = (const float*)d_in[11];
    const float* og_w_cn = (const float*)d_in[12];
    const float* og_w_h  = (const float*)d_in[13];
    const float* og_w_x  = (const float*)d_in[14];
    const float* og_b    = (const float*)d_in[15];
    float* out = (float*)d_out;

    timelstm_kernel<<<NBLK, THREADS>>>(
        x, ig_w_c, ig_w_h, ig_w_x, ig_b,
        fg_w_c, fg_w_h, fg_w_x, fg_b,
        in_w_h, in_w_x, in_b,
        og_w_cn, og_w_h, og_w_x, og_b, out);
}

// round 9
// speedup vs baseline: 1.0024x; 1.0024x over previous
#include <cuda_runtime.h>
#include <cstddef>

#define BB 2048
#define NN 512
#define XX 32
#define HH 64
#define TILE_B 8
#define THREADS 128
#define NBLK (BB / TILE_B)   /* 256 */
#define HPITCH 12            /* 48B pitch: 16B-aligned */
#define GPITCH 65

__device__ __forceinline__ unsigned long long pack2(float v) {
    unsigned long long r;
    asm("mov.b64 %0, {%1, %1};" : "=l"(r) : "f"(v));
    return r;
}
__device__ __forceinline__ unsigned long long fma2(unsigned long long a,
                                                   unsigned long long b,
                                                   unsigned long long c) {
    unsigned long long d;
    asm("fma.rn.f32x2 %0, %1, %2, %3;" : "=l"(d) : "l"(a), "l"(b), "l"(c));
    return d;
}
__device__ __forceinline__ void unpack2(unsigned long long v, float& lo, float& hi) {
    asm("mov.b64 {%0, %1}, %2;" : "=f"(lo), "=f"(hi) : "l"(v));
}

__device__ __forceinline__ float sigmoidf_fast(float x) {
    return __fdividef(1.0f, 1.0f + __expf(-x));
}
__device__ __forceinline__ float tanhf_fast(float x) {
    return __fdividef(2.0f, 1.0f + __expf(-2.0f * x)) - 1.0f;
}

__global__ void __launch_bounds__(THREADS, 2)
timelstm_kernel(const float* __restrict__ x,
                const float* __restrict__ ig_w_c, const float* __restrict__ ig_w_h,
                const float* __restrict__ ig_w_x, const float* __restrict__ ig_b,
                const float* __restrict__ fg_w_c, const float* __restrict__ fg_w_h,
                const float* __restrict__ fg_w_x, const float* __restrict__ fg_b,
                const float* __restrict__ in_w_h, const float* __restrict__ in_w_x,
                const float* __restrict__ in_b,
                const float* __restrict__ og_w_cn, const float* __restrict__ og_w_h,
                const float* __restrict__ og_w_x, const float* __restrict__ og_b,
                float* __restrict__ out)
{
    // ping-pong buffers: [buf][k][row], 16B-aligned rows
    __shared__ __align__(16) float h_sh[2][HH * HPITCH];
    __shared__ __align__(16) float x_sh[2][XX * HPITCH];
    __shared__ float g_sh[4][TILE_B][GPITCH];
    __shared__ float cm_sh[TILE_B][HH];
    __shared__ float wc_sh[3][HH];

    const int tid = threadIdx.x;
    const int b0  = blockIdx.x * TILE_B;
    const int p   = tid >> 6;      // gate pair: 0 -> (ig,fg), 1 -> (in,og)
    const int hid = tid & 63;      // output channel

    // ---- two full weight rows per thread ----
    const float *Wh0, *Wx0, *Bv0, *Wh1, *Wx1, *Bv1;
    if (p == 0) { Wh0 = ig_w_h; Wx0 = ig_w_x; Bv0 = ig_b;
                  Wh1 = fg_w_h; Wx1 = fg_w_x; Bv1 = fg_b; }
    else        { Wh0 = in_w_h; Wx0 = in_w_x; Bv0 = in_b;
                  Wh1 = og_w_h; Wx1 = og_w_x; Bv1 = og_b; }

    float w0x[XX], w1x[XX], w0h[HH], w1h[HH];
    #pragma unroll
    for (int j = 0; j < XX; j++) { w0x[j] = Wx0[hid * XX + j]; w1x[j] = Wx1[hid * XX + j]; }
    #pragma unroll
    for (int j = 0; j < HH; j++) { w0h[j] = Wh0[hid * HH + j]; w1h[j] = Wh1[hid * HH + j]; }
    const float bias0 = Bv0[hid];
    const float bias1 = Bv1[hid];

    if (tid < HH) {
        wc_sh[0][tid] = ig_w_c[tid];
        wc_sh[1][tid] = fg_w_c[tid];
        wc_sh[2][tid] = og_w_cn[tid];
    }
    for (int i = tid; i < HH * HPITCH; i += THREADS) h_sh[0][i] = 0.0f;
    for (int i = tid; i < TILE_B * HH; i += THREADS) (&cm_sh[0][0])[i] = 0.0f;

    // ---- x prefetch: 2 values/thread/step (8 rows x 32 k) ----
    const int xr = tid >> 5;   // rows xr and xr+4
    const int xk = tid & 31;
    const float* xp0 = x + ((size_t)(b0 + xr) * NN) * XX + xk;
    const float* xp1 = x + ((size_t)(b0 + xr + 4) * NN) * XX + xk;

    // prologue: deposit x(0) into buf 0, prefetch x(1) into regs
    float xv0 = xp0[0], xv1 = xp1[0];
    x_sh[0][xk * HPITCH + xr]     = xv0;
    x_sh[0][xk * HPITCH + xr + 4] = xv1;
    xv0 = xp0[XX];
    xv1 = xp1[XX];
    __syncthreads();   // x(0), h(0)=0, cm=0 all visible

    // xacc(0): acc = bias + x-projection of step 0
    unsigned long long a0[4], a1[4];
    {
        unsigned long long b0p = pack2(bias0), b1p = pack2(bias1);
        #pragma unroll
        for (int i = 0; i < 4; i++) { a0[i] = b0p; a1[i] = b1p; }
        #pragma unroll
        for (int k = 0; k < XX; k++) {
            const ulonglong2* ptr =
                reinterpret_cast<const ulonglong2*>(&x_sh[0][k * HPITCH]);
            ulonglong2 v0 = ptr[0], v1 = ptr[1];
            unsigned long long u0 = pack2(w0x[k]), u1 = pack2(w1x[k]);
            a0[0] = fma2(v0.x, u0, a0[0]); a0[1] = fma2(v0.y, u0, a0[1]);
            a0[2] = fma2(v1.x, u0, a0[2]); a0[3] = fma2(v1.y, u0, a0[3]);
            a1[0] = fma2(v0.x, u1, a1[0]); a1[1] = fma2(v0.y, u1, a1[1]);
            a1[2] = fma2(v1.x, u1, a1[2]); a1[3] = fma2(v1.y, u1, a1[3]);
        }
    }

    const int rb = tid >> 6;   // phase-B rows rb*4..rb*4+3 (p reused as rb? distinct name)
    const int hh = tid & 63;

    for (int t = 0; t < NN; t++) {
        const int buf  = t & 1;
        const int nbuf = buf ^ 1;

        // ---- W1: deposit x(t+1), then h-projection (acc already holds bias+x(t)) ----
        x_sh[nbuf][xk * HPITCH + xr]     = xv0;
        x_sh[nbuf][xk * HPITCH + xr + 4] = xv1;

        #pragma unroll
        for (int k = 0; k < HH; k++) {
            const ulonglong2* ptr =
                reinterpret_cast<const ulonglong2*>(&h_sh[buf][k * HPITCH]);
            ulonglong2 v0 = ptr[0], v1 = ptr[1];
            unsigned long long u0 = pack2(w0h[k]), u1 = pack2(w1h[k]);
            a0[0] = fma2(v0.x, u0, a0[0]); a0[1] = fma2(v0.y, u0, a0[1]);
            a0[2] = fma2(v1.x, u0, a0[2]); a0[3] = fma2(v1.y, u0, a0[3]);
            a1[0] = fma2(v0.x, u1, a1[0]); a1[1] = fma2(v0.y, u1, a1[1]);
            a1[2] = fma2(v1.x, u1, a1[2]); a1[3] = fma2(v1.y, u1, a1[3]);
        }
        #pragma unroll
        for (int i = 0; i < 4; i++) {
            float lo, hi;
            unpack2(a0[i], lo, hi);
            g_sh[2 * p][2 * i][hid]     = lo;
            g_sh[2 * p][2 * i + 1][hid] = hi;
            unpack2(a1[i], lo, hi);
            g_sh[2 * p + 1][2 * i][hid]     = lo;
            g_sh[2 * p + 1][2 * i + 1][hid] = hi;
        }
        __syncthreads();   // B2: g_sh ready, x(t+1) deposits visible

        // ---- W2: phase B (MUFU) overlapped with xacc(t+1) (fma) ----

        // issue x(t+2) prefetch first (long-latency LDG, consumed next iteration)
        if (t + 2 < NN) {
            xv0 = xp0[(size_t)(t + 2) * XX];
            xv1 = xp1[(size_t)(t + 2) * XX];
        }

        // phase B: 4 rows/thread, rows rb*4..rb*4+3, channel hh
        {
            const float wic = wc_sh[0][hh];
            const float wfc = wc_sh[1][hh];
            const float woc = wc_sh[2][hh];
            float hv[4];
            #pragma unroll
            for (int rr = 0; rr < 4; rr++) {
                const int r = rb * 4 + rr;
                const float cm  = cm_sh[r][hh];
                const float ig  = sigmoidf_fast(wic * cm + g_sh[0][r][hh]);
                const float fg  = sigmoidf_fast(wfc * cm + g_sh[1][r][hh]);
                const float inn = tanhf_fast(g_sh[2][r][hh]);
                const float cmn = fg * cm + ig * inn;
                const float og  = sigmoidf_fast(woc * cmn + g_sh[3][r][hh]);
                hv[rr] = og * tanhf_fast(cmn);
                cm_sh[r][hh] = cmn;
            }
            *reinterpret_cast<float4*>(&h_sh[nbuf][hh * HPITCH + rb * 4]) =
                make_float4(hv[0], hv[1], hv[2], hv[3]);
            if (t == NN - 1) {
                #pragma unroll
                for (int rr = 0; rr < 4; rr++)
                    out[(size_t)(b0 + rb * 4 + rr) * HH + hh] = hv[rr];
            }
        }

        // xacc(t+1): independent fma chains, overlap the MUFU above
        {
            unsigned long long b0p = pack2(bias0), b1p = pack2(bias1);
            #pragma unroll
            for (int i = 0; i < 4; i++) { a0[i] = b0p; a1[i] = b1p; }
            #pragma unroll
            for (int k = 0; k < XX; k++) {
                const ulonglong2* ptr =
                    reinterpret_cast<const ulonglong2*>(&x_sh[nbuf][k * HPITCH]);
                ulonglong2 v0 = ptr[0], v1 = ptr[1];
                unsigned long long u0 = pack2(w0x[k]), u1 = pack2(w1x[k]);
                a0[0] = fma2(v0.x, u0, a0[0]); a0[1] = fma2(v0.y, u0, a0[1]);
                a0[2] = fma2(v1.x, u0, a0[2]); a0[3] = fma2(v1.y, u0, a0[3]);
                a1[0] = fma2(v0.x, u1, a1[0]); a1[1] = fma2(v0.y, u1, a1[1]);
                a1[2] = fma2(v1.x, u1, a1[2]); a1[3] = fma2(v1.y, u1, a1[3]);
            }
        }
        __syncthreads();   // B1: h(t+1) ready; closes the step
    }
}

extern "C" void kernel_launch(void* const* d_in, const int* in_sizes, int n_in,
                              void* d_out, int out_size) {
    const float* x       = (const float*)d_in[0];
    const float* ig_w_c  = (const float*)d_in[1];
    const float* ig_w_h  = (const float*)d_in[2];
    const float* ig_w_x  = (const float*)d_in[3];
    const float* ig_b    = (const float*)d_in[4];
    const float* fg_w_c  = (const float*)d_in[5];
    const float* fg_w_h  = (const float*)d_in[6];
    const float* fg_w_x  = (const float*)d_in[7];
    const float* fg_b    = (const float*)d_in[8];
    const float* in_w_h  = (const float*)d_in[9];
    const float* in_w_x  = (const float*)d_in[10];
    const float* in_b    = (const float*)d_in[11];
    const float* og_w_cn = (const float*)d_in[12];
    const float* og_w_h  = (const float*)d_in[13];
    const float* og_w_x  = (const float*)d_in[14];
    const float* og_b    = (const float*)d_in[15];
    float* out = (float*)d_out;

    timelstm_kernel<<<NBLK, THREADS>>>(
        x, ig_w_c, ig_w_h, ig_w_x, ig_b,
        fg_w_c, fg_w_h, fg_w_x, fg_b,
        in_w_h, in_w_x, in_b,
        og_w_cn, og_w_h, og_w_x, og_b, out);
}

// round 10
// speedup vs baseline: 1.8746x; 1.8702x over previous
#include <cuda_runtime.h>
#include <cuda_bf16.h>
#include <cstddef>

#define BB 2048
#define NN 512
#define XX 32
#define HH 64
#define TILE_B 16
#define THREADS 256
#define NBLK (BB / TILE_B)   /* 128 */
#define KA 96                /* combined k: x(0..31) | h(32..95) */
#define APITCH 104           /* bf16 per row; 52*g+j bank map is conflict-free */
#define GPITCH 72            /* f32 per row in g_sh */

__device__ __forceinline__ float sigmoidf_fast(float x) {
    return __fdividef(1.0f, 1.0f + __expf(-x));
}
__device__ __forceinline__ float tanhf_fast(float x) {
    return __fdividef(2.0f, 1.0f + __expf(-2.0f * x)) - 1.0f;
}

// pack two bf16 values (a -> low half / element 0)
__device__ __forceinline__ unsigned bfpack(__nv_bfloat16 a, __nv_bfloat16 b) {
    __nv_bfloat162 t;
    t.x = a; t.y = b;
    return *reinterpret_cast<unsigned*>(&t);
}
// split fp32 into bf16 hi + bf16 lo (residual)
__device__ __forceinline__ void bsplit(float v, __nv_bfloat16& bh, __nv_bfloat16& bl) {
    bh = __float2bfloat16_rn(v);
    bl = __float2bfloat16_rn(v - __bfloat162float(bh));
}

__device__ __forceinline__ void mma16816(float* c, const unsigned* a, const unsigned* b) {
    asm volatile(
        "mma.sync.aligned.m16n8k16.row.col.f32.bf16.bf16.f32 "
        "{%0,%1,%2,%3}, {%4,%5,%6,%7}, {%8,%9}, {%0,%1,%2,%3};"
        : "+f"(c[0]), "+f"(c[1]), "+f"(c[2]), "+f"(c[3])
        : "r"(a[0]), "r"(a[1]), "r"(a[2]), "r"(a[3]), "r"(b[0]), "r"(b[1]));
}

__global__ void __launch_bounds__(THREADS, 1)
timelstm_tc_kernel(const float* __restrict__ x,
                   const float* __restrict__ ig_w_c, const float* __restrict__ ig_w_h,
                   const float* __restrict__ ig_w_x, const float* __restrict__ ig_b,
                   const float* __restrict__ fg_w_c, const float* __restrict__ fg_w_h,
                   const float* __restrict__ fg_w_x, const float* __restrict__ fg_b,
                   const float* __restrict__ in_w_h, const float* __restrict__ in_w_x,
                   const float* __restrict__ in_b,
                   const float* __restrict__ og_w_cn, const float* __restrict__ og_w_h,
                   const float* __restrict__ og_w_x, const float* __restrict__ og_b,
                   float* __restrict__ out)
{
    // A operand (hi/lo): [row][col], col 0..31 = x_t, col 32..95 = h_t
    __shared__ __align__(16) __nv_bfloat16 Ahi[TILE_B][APITCH];
    __shared__ __align__(16) __nv_bfloat16 Alo[TILE_B][APITCH];
    __shared__ float g_sh[4][TILE_B][GPITCH];   // gate pre-activations (no bias)

    const int tid  = threadIdx.x;
    const int b0   = blockIdx.x * TILE_B;
    const int warp = tid >> 5;
    const int lane = tid & 31;
    const int gate  = warp >> 1;     // 0 ig, 1 fg, 2 in, 3 og
    const int nhalf = warp & 1;      // which 32 output channels of the gate
    const int jn = lane >> 2;        // MMA group id (A/D row, B col)
    const int jk = (lane & 3) * 2;   // MMA k-local base (A/B k, D col)

    const float *Wh, *Wx;
    if (gate == 0)      { Wh = ig_w_h; Wx = ig_w_x; }
    else if (gate == 1) { Wh = fg_w_h; Wx = fg_w_x; }
    else if (gate == 2) { Wh = in_w_h; Wx = in_w_x; }
    else                { Wh = og_w_h; Wx = og_w_x; }

    // ---- B fragments (weights), hi and lo, loaded once ----
    // W_comb[k][n] = w[n][k] with k = combined (x|h), n = output channel
    unsigned Bh[6][4][2], Bl[6][4][2];
    #pragma unroll
    for (int kt = 0; kt < 6; kt++) {
        #pragma unroll
        for (int nt = 0; nt < 4; nt++) {
            const int ch = nhalf * 32 + nt * 8 + jn;
            #pragma unroll
            for (int r = 0; r < 2; r++) {
                const int k0 = kt * 16 + jk + r * 8;
                float v0 = (k0 < 32)     ? Wx[ch * XX + k0]       : Wh[ch * HH + (k0 - 32)];
                float v1 = (k0 + 1 < 32) ? Wx[ch * XX + k0 + 1]   : Wh[ch * HH + (k0 + 1 - 32)];
                __nv_bfloat16 h0, l0, h1, l1;
                bsplit(v0, h0, l0);
                bsplit(v1, h1, l1);
                Bh[kt][nt][r] = bfpack(h0, h1);
                Bl[kt][nt][r] = bfpack(l0, l1);
            }
        }
    }

    // ---- phase-B per-thread constants: rows {rg, rg+8}, channels {pc, pc+1} ----
    const int rg = tid >> 5;          // 0..7
    const int pc = (tid & 31) * 2;    // 0..62 even
    float bI[2], bF[2], bN[2], bO[2], wic[2], wfc[2], woc[2];
    #pragma unroll
    for (int c = 0; c < 2; c++) {
        bI[c] = ig_b[pc + c];  bF[c] = fg_b[pc + c];
        bN[c] = in_b[pc + c];  bO[c] = og_b[pc + c];
        wic[c] = ig_w_c[pc + c]; wfc[c] = fg_w_c[pc + c]; woc[c] = og_w_cn[pc + c];
    }
    float cm[2][2] = {{0.0f, 0.0f}, {0.0f, 0.0f}};

    // x loader mapping: one row, two channels per thread
    const int xrow = tid >> 4;          // 0..15
    const int xc2  = (tid & 15) * 2;    // 0..30
    const float* xptr = x + ((size_t)(b0 + xrow) * NN) * XX + xc2;

    // ---- prologue: zero A, deposit x(0) ----
    for (int i = tid; i < TILE_B * APITCH; i += THREADS) {
        (&Ahi[0][0])[i] = __float2bfloat16_rn(0.0f);
        (&Alo[0][0])[i] = __float2bfloat16_rn(0.0f);
    }
    __syncthreads();
    {
        float2 xv = *reinterpret_cast<const float2*>(xptr);
        __nv_bfloat16 h0, l0, h1, l1;
        bsplit(xv.x, h0, l0);
        bsplit(xv.y, h1, l1);
        *reinterpret_cast<unsigned*>(&Ahi[xrow][xc2]) = bfpack(h0, h1);
        *reinterpret_cast<unsigned*>(&Alo[xrow][xc2]) = bfpack(l0, l1);
    }
    __syncthreads();

    for (int t = 0; t < NN; t++) {
        // prefetch x(t+1) early (consumed in phase B)
        float2 xn = make_float2(0.0f, 0.0f);
        if (t + 1 < NN)
            xn = *reinterpret_cast<const float2*>(xptr + (size_t)(t + 1) * XX);

        // ---- phase A: 3-term split GEMM, acc starts at 0 (bias added in phase B) ----
        float acc[4][4];
        #pragma unroll
        for (int nt = 0; nt < 4; nt++)
            #pragma unroll
            for (int i = 0; i < 4; i++) acc[nt][i] = 0.0f;

        unsigned a[4];
        #pragma unroll
        for (int kt = 0; kt < 6; kt++) {
            const int kc = kt * 16 + jk;
            a[0] = *reinterpret_cast<const unsigned*>(&Ahi[jn][kc]);
            a[1] = *reinterpret_cast<const unsigned*>(&Ahi[jn + 8][kc]);
            a[2] = *reinterpret_cast<const unsigned*>(&Ahi[jn][kc + 8]);
            a[3] = *reinterpret_cast<const unsigned*>(&Ahi[jn + 8][kc + 8]);
            #pragma unroll
            for (int nt = 0; nt < 4; nt++) mma16816(acc[nt], a, Bh[kt][nt]);  // hi*hi
            #pragma unroll
            for (int nt = 0; nt < 4; nt++) mma16816(acc[nt], a, Bl[kt][nt]);  // hi*lo
        }
        #pragma unroll
        for (int kt = 0; kt < 6; kt++) {
            const int kc = kt * 16 + jk;
            a[0] = *reinterpret_cast<const unsigned*>(&Alo[jn][kc]);
            a[1] = *reinterpret_cast<const unsigned*>(&Alo[jn + 8][kc]);
            a[2] = *reinterpret_cast<const unsigned*>(&Alo[jn][kc + 8]);
            a[3] = *reinterpret_cast<const unsigned*>(&Alo[jn + 8][kc + 8]);
            #pragma unroll
            for (int nt = 0; nt < 4; nt++) mma16816(acc[nt], a, Bh[kt][nt]);  // lo*hi
        }

        // scatter D frags to g_sh: rows {jn, jn+8}, cols jk within each n-tile
        #pragma unroll
        for (int nt = 0; nt < 4; nt++) {
            const int ch = nhalf * 32 + nt * 8 + jk;
            *reinterpret_cast<float2*>(&g_sh[gate][jn][ch])     = make_float2(acc[nt][0], acc[nt][1]);
            *reinterpret_cast<float2*>(&g_sh[gate][jn + 8][ch]) = make_float2(acc[nt][2], acc[nt][3]);
        }
        __syncthreads();   // B1: g_sh complete; all A reads for step t done

        // ---- phase B: activations + state update; write h(t+1), x(t+1) into A ----
        float hnew[2][2];
        #pragma unroll
        for (int e = 0; e < 2; e++) {
            const int r = rg + 8 * e;
            #pragma unroll
            for (int c = 0; c < 2; c++) {
                const int ch = pc + c;
                const float cmv = cm[e][c];
                const float ig  = sigmoidf_fast(wic[c] * cmv + g_sh[0][r][ch] + bI[c]);
                const float fg  = sigmoidf_fast(wfc[c] * cmv + g_sh[1][r][ch] + bF[c]);
                const float inn = tanhf_fast(g_sh[2][r][ch] + bN[c]);
                const float cmn = fg * cmv + ig * inn;
                const float og  = sigmoidf_fast(woc[c] * cmn + g_sh[3][r][ch] + bO[c]);
                hnew[e][c] = og * tanhf_fast(cmn);
                cm[e][c] = cmn;
            }
            // h -> bf16 split into A cols 32..95
            __nv_bfloat16 h0, l0, h1, l1;
            bsplit(hnew[e][0], h0, l0);
            bsplit(hnew[e][1], h1, l1);
            *reinterpret_cast<unsigned*>(&Ahi[r][32 + pc]) = bfpack(h0, h1);
            *reinterpret_cast<unsigned*>(&Alo[r][32 + pc]) = bfpack(l0, l1);
        }
        // x(t+1) -> bf16 split into A cols 0..31
        if (t + 1 < NN) {
            __nv_bfloat16 h0, l0, h1, l1;
            bsplit(xn.x, h0, l0);
            bsplit(xn.y, h1, l1);
            *reinterpret_cast<unsigned*>(&Ahi[xrow][xc2]) = bfpack(h0, h1);
            *reinterpret_cast<unsigned*>(&Alo[xrow][xc2]) = bfpack(l0, l1);
        }
        if (t == NN - 1) {
            *reinterpret_cast<float2*>(&out[(size_t)(b0 + rg) * HH + pc]) =
                make_float2(hnew[0][0], hnew[0][1]);
            *reinterpret_cast<float2*>(&out[(size_t)(b0 + rg + 8) * HH + pc]) =
                make_float2(hnew[1][0], hnew[1][1]);
        }
        __syncthreads();   // B2: new A ready for step t+1
    }
}

extern "C" void kernel_launch(void* const* d_in, const int* in_sizes, int n_in,
                              void* d_out, int out_size) {
    const float* x       = (const float*)d_in[0];
    const float* ig_w_c  = (const float*)d_in[1];
    const float* ig_w_h  = (const float*)d_in[2];
    const float* ig_w_x  = (const float*)d_in[3];
    const float* ig_b    = (const float*)d_in[4];
    const float* fg_w_c  = (const float*)d_in[5];
    const float* fg_w_h  = (const float*)d_in[6];
    const float* fg_w_x  = (const float*)d_in[7];
    const float* fg_b    = (const float*)d_in[8];
    const float* in_w_h  = (const float*)d_in[9];
    const float* in_w_x  = (const float*)d_in[10];
    const float* in_b    = (const float*)d_in[11];
    const float* og_w_cn = (const float*)d_in[12];
    const float* og_w_h  = (const float*)d_in[13];
    const float* og_w_x  = (const float*)d_in[14];
    const float* og_b    = (const float*)d_in[15];
    float* out = (float*)d_out;

    timelstm_tc_kernel<<<NBLK, THREADS>>>(
        x, ig_w_c, ig_w_h, ig_w_x, ig_b,
        fg_w_c, fg_w_h, fg_w_x, fg_b,
        in_w_h, in_w_x, in_b,
        og_w_cn, og_w_h, og_w_x, og_b, out);
}

// round 13
// speedup vs baseline: 1.9741x; 1.0531x over previous
#include <cuda_runtime.h>
#include <cuda_bf16.h>
#include <cstddef>

#define BB 2048
#define NN 512
#define XX 32
#define HH 64
#define TILE_B 16
#define THREADS 256
#define NBLK (BB / TILE_B)   /* 128 */
#define AXP 40               /* x operand pitch (bf16): 20 words, conflict-free */
#define AHP 72               /* h operand pitch (bf16): 36 words, conflict-free */
#define GPITCH 72            /* f32 per row in g_sh */

__device__ __forceinline__ float sigmoidf_fast(float x) {
    return __fdividef(1.0f, 1.0f + __expf(-x));
}
__device__ __forceinline__ float tanhf_fast(float x) {
    return __fdividef(2.0f, 1.0f + __expf(-2.0f * x)) - 1.0f;
}

__device__ __forceinline__ unsigned bfpack(__nv_bfloat16 a, __nv_bfloat16 b) {
    __nv_bfloat162 t;
    t.x = a; t.y = b;
    return *reinterpret_cast<unsigned*>(&t);
}
__device__ __forceinline__ void bsplit(float v, __nv_bfloat16& bh, __nv_bfloat16& bl) {
    bh = __float2bfloat16_rn(v);
    bl = __float2bfloat16_rn(v - __bfloat162float(bh));
}

__device__ __forceinline__ void mma16816(float* c, const unsigned* a, const unsigned* b) {
    asm volatile(
        "mma.sync.aligned.m16n8k16.row.col.f32.bf16.bf16.f32 "
        "{%0,%1,%2,%3}, {%4,%5,%6,%7}, {%8,%9}, {%0,%1,%2,%3};"
        : "+f"(c[0]), "+f"(c[1]), "+f"(c[2]), "+f"(c[3])
        : "r"(a[0]), "r"(a[1]), "r"(a[2]), "r"(a[3]), "r"(b[0]), "r"(b[1]));
}

__global__ void __launch_bounds__(THREADS, 1)
timelstm_tc_kernel(const float* __restrict__ x,
                   const float* __restrict__ ig_w_c, const float* __restrict__ ig_w_h,
                   const float* __restrict__ ig_w_x, const float* __restrict__ ig_b,
                   const float* __restrict__ fg_w_c, const float* __restrict__ fg_w_h,
                   const float* __restrict__ fg_w_x, const float* __restrict__ fg_b,
                   const float* __restrict__ in_w_h, const float* __restrict__ in_w_x,
                   const float* __restrict__ in_b,
                   const float* __restrict__ og_w_cn, const float* __restrict__ og_w_h,
                   const float* __restrict__ og_w_x, const float* __restrict__ og_b,
                   float* __restrict__ out)
{
    // ping-pong operands: x cols 0..31, h cols 0..63 (separate arrays)
    __shared__ __align__(16) __nv_bfloat16 Axhi[2][TILE_B][AXP];
    __shared__ __align__(16) __nv_bfloat16 Axlo[2][TILE_B][AXP];
    __shared__ __align__(16) __nv_bfloat16 Ahhi[2][TILE_B][AHP];
    __shared__ __align__(16) __nv_bfloat16 Ahlo[2][TILE_B][AHP];
    __shared__ float g_sh[4][TILE_B][GPITCH];

    const int tid  = threadIdx.x;
    const int b0   = blockIdx.x * TILE_B;
    const int warp = tid >> 5;
    const int lane = tid & 31;
    const int gate  = warp >> 1;     // 0 ig, 1 fg, 2 in, 3 og
    const int nhalf = warp & 1;
    const int jn = lane >> 2;
    const int jk = (lane & 3) * 2;

    const float *Wh, *Wx;
    if (gate == 0)      { Wh = ig_w_h; Wx = ig_w_x; }
    else if (gate == 1) { Wh = fg_w_h; Wx = fg_w_x; }
    else if (gate == 2) { Wh = in_w_h; Wx = in_w_x; }
    else                { Wh = og_w_h; Wx = og_w_x; }

    // ---- B fragments: kt 0..1 = x-part, kt 2..5 = h-part ----
    unsigned Bh[6][4][2], Bl[6][4][2];
    #pragma unroll
    for (int kt = 0; kt < 6; kt++) {
        #pragma unroll
        for (int nt = 0; nt < 4; nt++) {
            const int ch = nhalf * 32 + nt * 8 + jn;
            #pragma unroll
            for (int r = 0; r < 2; r++) {
                const int k0 = kt * 16 + jk + r * 8;
                float v0 = (k0 < 32)     ? Wx[ch * XX + k0]     : Wh[ch * HH + (k0 - 32)];
                float v1 = (k0 + 1 < 32) ? Wx[ch * XX + k0 + 1] : Wh[ch * HH + (k0 + 1 - 32)];
                __nv_bfloat16 h0, l0, h1, l1;
                bsplit(v0, h0, l0);
                bsplit(v1, h1, l1);
                Bh[kt][nt][r] = bfpack(h0, h1);
                Bl[kt][nt][r] = bfpack(l0, l1);
            }
        }
    }

    // ---- phase-B constants ----
    const int rg = tid >> 5;
    const int pc = (tid & 31) * 2;
    float bI[2], bF[2], bN[2], bO[2], wic[2], wfc[2], woc[2];
    #pragma unroll
    for (int c = 0; c < 2; c++) {
        bI[c] = ig_b[pc + c];  bF[c] = fg_b[pc + c];
        bN[c] = in_b[pc + c];  bO[c] = og_b[pc + c];
        wic[c] = ig_w_c[pc + c]; wfc[c] = fg_w_c[pc + c]; woc[c] = og_w_cn[pc + c];
    }
    float cm[2][2] = {{0.0f, 0.0f}, {0.0f, 0.0f}};

    // x loader mapping
    const int xrow = tid >> 4;
    const int xc2  = (tid & 15) * 2;
    const float* xptr = x + ((size_t)(b0 + xrow) * NN) * XX + xc2;

    // ---- prologue: zero Ah[0]; deposit x(0) into Ax[0] ----
    for (int i = tid; i < TILE_B * AHP; i += THREADS) {
        (&Ahhi[0][0][0])[i] = __float2bfloat16_rn(0.0f);
        (&Ahlo[0][0][0])[i] = __float2bfloat16_rn(0.0f);
    }
    {
        float2 xv = *reinterpret_cast<const float2*>(xptr);
        __nv_bfloat16 h0, l0, h1, l1;
        bsplit(xv.x, h0, l0);
        bsplit(xv.y, h1, l1);
        *reinterpret_cast<unsigned*>(&Axhi[0][xrow][xc2]) = bfpack(h0, h1);
        *reinterpret_cast<unsigned*>(&Axlo[0][xrow][xc2]) = bfpack(l0, l1);
    }
    __syncthreads();

    float acc[4][4];
    unsigned a[4];

    // x-contrib(0) from Ax[0]
    #pragma unroll
    for (int nt = 0; nt < 4; nt++)
        #pragma unroll
        for (int i = 0; i < 4; i++) acc[nt][i] = 0.0f;
    #pragma unroll
    for (int kt = 0; kt < 2; kt++) {
        const int kc = kt * 16 + jk;
        a[0] = *reinterpret_cast<const unsigned*>(&Axhi[0][jn][kc]);
        a[1] = *reinterpret_cast<const unsigned*>(&Axhi[0][jn + 8][kc]);
        a[2] = *reinterpret_cast<const unsigned*>(&Axhi[0][jn][kc + 8]);
        a[3] = *reinterpret_cast<const unsigned*>(&Axhi[0][jn + 8][kc + 8]);
        #pragma unroll
        for (int nt = 0; nt < 4; nt++) mma16816(acc[nt], a, Bh[kt][nt]);
        #pragma unroll
        for (int nt = 0; nt < 4; nt++) mma16816(acc[nt], a, Bl[kt][nt]);
        a[0] = *reinterpret_cast<const unsigned*>(&Axlo[0][jn][kc]);
        a[1] = *reinterpret_cast<const unsigned*>(&Axlo[0][jn + 8][kc]);
        a[2] = *reinterpret_cast<const unsigned*>(&Axlo[0][jn][kc + 8]);
        a[3] = *reinterpret_cast<const unsigned*>(&Axlo[0][jn + 8][kc + 8]);
        #pragma unroll
        for (int nt = 0; nt < 4; nt++) mma16816(acc[nt], a, Bh[kt][nt]);
    }
    // prefetch x(1)
    float2 xn = *reinterpret_cast<const float2*>(xptr + (size_t)1 * XX);

    for (int t = 0; t < NN; t++) {
        const int buf  = t & 1;
        const int nbuf = buf ^ 1;

        // ---- W1: deposit x(t+1); h-MMA (kt 2..5) into acc (holds x-contrib(t)) ----
        {
            __nv_bfloat16 h0, l0, h1, l1;
            bsplit(xn.x, h0, l0);
            bsplit(xn.y, h1, l1);
            *reinterpret_cast<unsigned*>(&Axhi[nbuf][xrow][xc2]) = bfpack(h0, h1);
            *reinterpret_cast<unsigned*>(&Axlo[nbuf][xrow][xc2]) = bfpack(l0, l1);
        }

        #pragma unroll
        for (int kt = 2; kt < 6; kt++) {
            const int hc = (kt - 2) * 16 + jk;
            a[0] = *reinterpret_cast<const unsigned*>(&Ahhi[buf][jn][hc]);
            a[1] = *reinterpret_cast<const unsigned*>(&Ahhi[buf][jn + 8][hc]);
            a[2] = *reinterpret_cast<const unsigned*>(&Ahhi[buf][jn][hc + 8]);
            a[3] = *reinterpret_cast<const unsigned*>(&Ahhi[buf][jn + 8][hc + 8]);
            #pragma unroll
            for (int nt = 0; nt < 4; nt++) mma16816(acc[nt], a, Bh[kt][nt]);
            #pragma unroll
            for (int nt = 0; nt < 4; nt++) mma16816(acc[nt], a, Bl[kt][nt]);
        }
        #pragma unroll
        for (int kt = 2; kt < 6; kt++) {
            const int hc = (kt - 2) * 16 + jk;
            a[0] = *reinterpret_cast<const unsigned*>(&Ahlo[buf][jn][hc]);
            a[1] = *reinterpret_cast<const unsigned*>(&Ahlo[buf][jn + 8][hc]);
            a[2] = *reinterpret_cast<const unsigned*>(&Ahlo[buf][jn][hc + 8]);
            a[3] = *reinterpret_cast<const unsigned*>(&Ahlo[buf][jn + 8][hc + 8]);
            #pragma unroll
            for (int nt = 0; nt < 4; nt++) mma16816(acc[nt], a, Bh[kt][nt]);
        }

        #pragma unroll
        for (int nt = 0; nt < 4; nt++) {
            const int ch = nhalf * 32 + nt * 8 + jk;
            *reinterpret_cast<float2*>(&g_sh[gate][jn][ch])     = make_float2(acc[nt][0], acc[nt][1]);
            *reinterpret_cast<float2*>(&g_sh[gate][jn + 8][ch]) = make_float2(acc[nt][2], acc[nt][3]);
        }
        __syncthreads();   // B1: g_sh + x(t+1) deposits visible

        // ---- W2: phase B (MUFU) overlapped with x-MMA(t+1) (tensor) ----
        if (t + 2 < NN)
            xn = *reinterpret_cast<const float2*>(xptr + (size_t)(t + 2) * XX);

        // x-MMA for t+1 into fresh acc (tensor pipe; independent of phase B)
        if (t + 1 < NN) {
            #pragma unroll
            for (int nt = 0; nt < 4; nt++)
                #pragma unroll
                for (int i = 0; i < 4; i++) acc[nt][i] = 0.0f;
            #pragma unroll
            for (int kt = 0; kt < 2; kt++) {
                const int kc = kt * 16 + jk;
                a[0] = *reinterpret_cast<const unsigned*>(&Axhi[nbuf][jn][kc]);
                a[1] = *reinterpret_cast<const unsigned*>(&Axhi[nbuf][jn + 8][kc]);
                a[2] = *reinterpret_cast<const unsigned*>(&Axhi[nbuf][jn][kc + 8]);
                a[3] = *reinterpret_cast<const unsigned*>(&Axhi[nbuf][jn + 8][kc + 8]);
                #pragma unroll
                for (int nt = 0; nt < 4; nt++) mma16816(acc[nt], a, Bh[kt][nt]);
                #pragma unroll
                for (int nt = 0; nt < 4; nt++) mma16816(acc[nt], a, Bl[kt][nt]);
                a[0] = *reinterpret_cast<const unsigned*>(&Axlo[nbuf][jn][kc]);
                a[1] = *reinterpret_cast<const unsigned*>(&Axlo[nbuf][jn + 8][kc]);
                a[2] = *reinterpret_cast<const unsigned*>(&Axlo[nbuf][jn][kc + 8]);
                a[3] = *reinterpret_cast<const unsigned*>(&Axlo[nbuf][jn + 8][kc + 8]);
                #pragma unroll
                for (int nt = 0; nt < 4; nt++) mma16816(acc[nt], a, Bh[kt][nt]);
            }
        }

        // phase B: activations + state update
        float hnew[2][2];
        #pragma unroll
        for (int e = 0; e < 2; e++) {
            const int r = rg + 8 * e;
            #pragma unroll
            for (int c = 0; c < 2; c++) {
                const int ch = pc + c;
                const float cmv = cm[e][c];
                const float ig  = sigmoidf_fast(wic[c] * cmv + g_sh[0][r][ch] + bI[c]);
                const float fg  = sigmoidf_fast(wfc[c] * cmv + g_sh[1][r][ch] + bF[c]);
                const float inn = tanhf_fast(g_sh[2][r][ch] + bN[c]);
                const float cmn = fg * cmv + ig * inn;
                const float og  = sigmoidf_fast(woc[c] * cmn + g_sh[3][r][ch] + bO[c]);
                hnew[e][c] = og * tanhf_fast(cmn);
                cm[e][c] = cmn;
            }
            __nv_bfloat16 h0, l0, h1, l1;
            bsplit(hnew[e][0], h0, l0);
            bsplit(hnew[e][1], h1, l1);
            *reinterpret_cast<unsigned*>(&Ahhi[nbuf][r][pc]) = bfpack(h0, h1);
            *reinterpret_cast<unsigned*>(&Ahlo[nbuf][r][pc]) = bfpack(l0, l1);
        }
        if (t == NN - 1) {
            *reinterpret_cast<float2*>(&out[(size_t)(b0 + rg) * HH + pc]) =
                make_float2(hnew[0][0], hnew[0][1]);
            *reinterpret_cast<float2*>(&out[(size_t)(b0 + rg + 8) * HH + pc]) =
                make_float2(hnew[1][0], hnew[1][1]);
        }
        __syncthreads();   // B2: h(t+1) ready; x-MMA reads of Ax[nbuf] complete
    }
}

extern "C" void kernel_launch(void* const* d_in, const int* in_sizes, int n_in,
                              void* d_out, int out_size) {
    const float* x       = (const float*)d_in[0];
    const float* ig_w_c  = (const float*)d_in[1];
    const float* ig_w_h  = (const float*)d_in[2];
    const float* ig_w_x  = (const float*)d_in[3];
    const float* ig_b    = (const float*)d_in[4];
    const float* fg_w_c  = (const float*)d_in[5];
    const float* fg_w_h  = (const float*)d_in[6];
    const float* fg_w_x  = (const float*)d_in[7];
    const float* fg_b    = (const float*)d_in[8];
    const float* in_w_h  = (const float*)d_in[9];
    const float* in_w_x  = (const float*)d_in[10];
    const float* in_b    = (const float*)d_in[11];
    const float* og_w_cn = (const float*)d_in[12];
    const float* og_w_h  = (const float*)d_in[13];
    const float* og_w_x  = (const float*)d_in[14];
    const float* og_b    = (const float*)d_in[15];
    float* out = (float*)d_out;

    timelstm_tc_kernel<<<NBLK, THREADS>>>(
        x, ig_w_c, ig_w_h, ig_w_x, ig_b,
        fg_w_c, fg_w_h, fg_w_x, fg_b,
        in_w_h, in_w_x, in_b,
        og_w_cn, og_w_h, og_w_x, og_b, out);
}